// round 1
// baseline (speedup 1.0000x reference)
#include <cuda_runtime.h>
#include <math.h>

// Problem constants
#define B_  16
#define C_  3
#define H_  512
#define W_  512
#define HW_ (H_ * W_)
#define KSZ 7
#define PAD 3
#define NDIV 147.0f            // C*K*K fixed divisor
#define EPS 1e-8f

#define TILE 32
#define EX   (TILE + KSZ - 1)  // 38
#define CSW  40                // padded row stride for cs/cs2
#define HSW  TILE              // row stride for hsum arrays

#define NTHREADS 256           // 32 x 8

__global__ void zero_out(float* out) { out[0] = 0.0f; }

__device__ __forceinline__ void load_and_channel_reduce(
    const float* __restrict__ plane0, int y0, int x0,
    float* cs, float* cs2, int tid)
{
    for (int i = tid; i < EX * EX; i += NTHREADS) {
        int r = i / EX, c = i - r * EX;
        int gy = y0 - PAD + r;
        int gx = x0 - PAD + c;
        float v0 = 0.f, v1 = 0.f, v2 = 0.f;
        if (gy >= 0 && gy < H_ && gx >= 0 && gx < W_) {
            int off = gy * W_ + gx;
            v0 = plane0[off];
            v1 = plane0[off + HW_];
            v2 = plane0[off + 2 * HW_];
        }
        cs [i / EX * CSW + c] = v0 + v1 + v2;
        cs2[i / EX * CSW + c] = v0 * v0 + v1 * v1 + v2 * v2;
    }
}

__global__ __launch_bounds__(NTHREADS)
void dist_loss_kernel(const float* __restrict__ pred,
                      const float* __restrict__ tgt,
                      float* __restrict__ out)
{
    __shared__ float cs [EX * CSW];
    __shared__ float cs2[EX * CSW];
    __shared__ float hs [EX * HSW];
    __shared__ float hs2[EX * HSW];
    __shared__ float warp_sums[NTHREADS / 32];

    const int tid = threadIdx.y * 32 + threadIdx.x;
    const int tx = threadIdx.x;           // 0..31 (column in tile)
    const int ty = threadIdx.y;           // 0..7
    const int x0 = blockIdx.x * TILE;
    const int y0 = blockIdx.y * TILE;
    const int b  = blockIdx.z;

    const float inv_n = 1.0f / NDIV;

    float std_p[4], std_t[4];

    const float* bases[2] = { pred + (size_t)b * C_ * HW_,
                              tgt  + (size_t)b * C_ * HW_ };

    for (int which = 0; which < 2; which++) {
        // ---- channel-reduced tile load (with halo) ----
        load_and_channel_reduce(bases[which], y0, x0, cs, cs2, tid);
        __syncthreads();

        // ---- horizontal 7-sum: (EX rows) x (TILE cols) ----
        for (int i = tid; i < EX * TILE; i += NTHREADS) {
            int r = i / TILE, c = i - r * TILE;
            float a = 0.f, a2 = 0.f;
            const float* pr  = &cs [r * CSW + c];
            const float* pr2 = &cs2[r * CSW + c];
            #pragma unroll
            for (int k = 0; k < KSZ; k++) { a += pr[k]; a2 += pr2[k]; }
            hs [r * HSW + c] = a;
            hs2[r * HSW + c] = a2;
        }
        __syncthreads();

        // ---- vertical 7-sum + std, 4 rows per thread ----
        #pragma unroll
        for (int j = 0; j < 4; j++) {
            int row = ty + j * 8;
            float a = 0.f, a2 = 0.f;
            #pragma unroll
            for (int k = 0; k < KSZ; k++) {
                a  += hs [(row + k) * HSW + tx];
                a2 += hs2[(row + k) * HSW + tx];
            }
            float mu  = a * inv_n;
            float var = a2 * inv_n - mu * mu;
            float sd  = sqrtf(var + EPS);
            if (which == 0) std_p[j] = sd; else std_t[j] = sd;
        }
        __syncthreads();   // before next input overwrites smem
    }

    // ---- smooth-L1 over this thread's 4 pixels ----
    float acc = 0.f;
    #pragma unroll
    for (int j = 0; j < 4; j++) {
        float d  = std_p[j] - std_t[j];
        float ad = fabsf(d);
        acc += (ad < 1.0f) ? 0.5f * d * d : ad - 0.5f;
    }

    // ---- block reduction ----
    #pragma unroll
    for (int off = 16; off > 0; off >>= 1)
        acc += __shfl_xor_sync(0xffffffffu, acc, off);
    if (tx == 0) warp_sums[ty] = acc;
    __syncthreads();
    if (tid == 0) {
        float s = 0.f;
        #pragma unroll
        for (int w = 0; w < NTHREADS / 32; w++) s += warp_sums[w];
        const float inv_count = 1.0f / ((float)B_ * (float)HW_);
        atomicAdd(out, s * inv_count);
    }
}

extern "C" void kernel_launch(void* const* d_in, const int* in_sizes, int n_in,
                              void* d_out, int out_size)
{
    const float* pred = (const float*)d_in[0];
    const float* tgt  = (const float*)d_in[1];
    float* out = (float*)d_out;

    zero_out<<<1, 1>>>(out);

    dim3 block(32, 8, 1);
    dim3 grid(W_ / TILE, H_ / TILE, B_);   // 16 x 16 x 16 = 4096 CTAs
    dist_loss_kernel<<<grid, block>>>(pred, tgt, out);
}

// round 2
// speedup vs baseline: 1.0864x; 1.0864x over previous
#include <cuda_runtime.h>
#include <math.h>

#define W_   512
#define H_   512
#define HW_  (512 * 512)
#define EPS  1e-8f
#define TW   58            // output columns per CTA (58 + 6 halo = 64 = 2 regs/lane)
#define FULLMASK 0xffffffffu

// rotate a 64-wide lane-distributed vector (lo = v[0..31], hi = v[32..63]) left by k:
// out[c] = v[c+k]
__device__ __forceinline__ void rot64(float xl, float xh, int k, int L,
                                      float& ol, float& oh) {
    int j = L + k;
    float a = __shfl_sync(FULLMASK, xl, j & 31);
    float b = __shfl_sync(FULLMASK, xh, j & 31);
    ol = (j < 32) ? a : b;
    oh = b;
}

// h[c] = sum_{k=0..6} v[c+k], via 7 = 4 + 2 + 1 decomposition (8 shfls)
__device__ __forceinline__ void hsum7(float vl, float vh, int L,
                                      float& hl, float& hh) {
    float r1l, r1h, r2l, r2h, r4l, r4h, r6l, r6h;
    rot64(vl, vh, 1, L, r1l, r1h);
    float d1l = vl + r1l, d1h = vh + r1h;      // 2-sum
    rot64(d1l, d1h, 2, L, r2l, r2h);
    float d2l = d1l + r2l, d2h = d1h + r2h;    // 4-sum
    rot64(d1l, d1h, 4, L, r4l, r4h);           // v[c+4]+v[c+5]
    rot64(vl, vh, 6, L, r6l, r6h);             // v[c+6]
    hl = d2l + (r4l + r6l);
    hh = d2h + (r4h + r6h);
}

__device__ __forceinline__ float smooth_l1(float a, float b) {
    float d = a - b;
    float ad = fabsf(d);
    return (ad < 1.0f) ? 0.5f * d * d : ad - 0.5f;
}

// One input row: load 2x3 channel values per lane, channel-reduce, horizontal
// 7-sum via shuffles, update vertical running sums through a 7-slot ring
// (compile-time slot S), and if past warm-up emit smooth-L1 contribution.
template <int S>
__device__ __forceinline__ void rowstep(
    const float* __restrict__ P, const float* __restrict__ T,
    int gxl, int gxh, bool okl, bool okh, bool hi_out, int L, int oy0,
    int& i, float (&ring)[8][7], float (&vs)[8], float& acc, float inv_n)
{
    int gy = oy0 - 3 + i;
    bool oky = (gy >= 0) && (gy < H_);
    bool lp = oky && okl;
    bool hp = oky && okh;
    const float* p0 = P + ((size_t)gy << 9);
    const float* t0 = T + ((size_t)gy << 9);

    float hv[8];
    {   // pred
        float a0 = lp ? p0[gxl]           : 0.f;
        float a1 = lp ? p0[gxl + HW_]     : 0.f;
        float a2 = lp ? p0[gxl + 2 * HW_] : 0.f;
        float b0 = hp ? p0[gxh]           : 0.f;
        float b1 = hp ? p0[gxh + HW_]     : 0.f;
        float b2 = hp ? p0[gxh + 2 * HW_] : 0.f;
        float vl  = a0 + a1 + a2;
        float vh  = b0 + b1 + b2;
        float vl2 = a0 * a0 + a1 * a1 + a2 * a2;
        float vh2 = b0 * b0 + b1 * b1 + b2 * b2;
        hsum7(vl,  vh,  L, hv[0], hv[2]);
        hsum7(vl2, vh2, L, hv[1], hv[3]);
    }
    {   // target
        float a0 = lp ? t0[gxl]           : 0.f;
        float a1 = lp ? t0[gxl + HW_]     : 0.f;
        float a2 = lp ? t0[gxl + 2 * HW_] : 0.f;
        float b0 = hp ? t0[gxh]           : 0.f;
        float b1 = hp ? t0[gxh + HW_]     : 0.f;
        float b2 = hp ? t0[gxh + 2 * HW_] : 0.f;
        float vl  = a0 + a1 + a2;
        float vh  = b0 + b1 + b2;
        float vl2 = a0 * a0 + a1 * a1 + a2 * a2;
        float vh2 = b0 * b0 + b1 * b1 + b2 * b2;
        hsum7(vl,  vh,  L, hv[4], hv[6]);
        hsum7(vl2, vh2, L, hv[5], hv[7]);
    }

#pragma unroll
    for (int a = 0; a < 8; a++) {
        vs[a] += hv[a] - ring[a][S];   // ring[a][S] holds h from 7 rows ago (0 in warm-up)
        ring[a][S] = hv[a];
    }

    if (i >= 6) {
        // lo column (always a valid pixel)
        float mpl = vs[0] * inv_n;
        float spl = sqrtf(fmaf(-mpl, mpl, vs[1] * inv_n) + EPS);
        float mtl = vs[4] * inv_n;
        float stl = sqrtf(fmaf(-mtl, mtl, vs[5] * inv_n) + EPS);
        acc += smooth_l1(spl, stl);
        if (hi_out) {
            float mph = vs[2] * inv_n;
            float sph = sqrtf(fmaf(-mph, mph, vs[3] * inv_n) + EPS);
            float mth = vs[6] * inv_n;
            float sth = sqrtf(fmaf(-mth, mth, vs[7] * inv_n) + EPS);
            acc += smooth_l1(sph, sth);
        }
    }
    i++;
}

__global__ __launch_bounds__(256, 2)
void dist_loss_kernel(const float* __restrict__ pred,
                      const float* __restrict__ tgt,
                      float* __restrict__ out)
{
    const int L  = threadIdx.x & 31;
    const int w  = threadIdx.x >> 5;
    const int x0 = blockIdx.x * TW;
    const int oy0 = (blockIdx.y << 8) + (w << 5);   // warp's first output row
    const size_t bofs = (size_t)blockIdx.z * 3 * HW_;
    const float* P = pred + bofs;
    const float* T = tgt + bofs;

    const int gxl = x0 - 3 + L;        // halo-inclusive column, low half
    const int gxh = x0 + 29 + L;       // high half
    const bool okl = (gxl >= 0) && (gxl < W_);
    const bool okh = (gxh < W_);
    const bool hi_out = (L <= 25) && ((x0 + 32 + L) < W_);

    const float inv_n = 1.0f / 147.0f;

    float ring[8][7];
    float vs[8];
#pragma unroll
    for (int a = 0; a < 8; a++) {
        vs[a] = 0.f;
#pragma unroll
        for (int j = 0; j < 7; j++) ring[a][j] = 0.f;
    }

    float acc = 0.f;
    int i = 0;

    // 38 input rows = 5 chunks of 7 (ring slots 0..6) + 3 tail steps
#pragma unroll 1
    for (int c = 0; c < 5; c++) {
        rowstep<0>(P, T, gxl, gxh, okl, okh, hi_out, L, oy0, i, ring, vs, acc, inv_n);
        rowstep<1>(P, T, gxl, gxh, okl, okh, hi_out, L, oy0, i, ring, vs, acc, inv_n);
        rowstep<2>(P, T, gxl, gxh, okl, okh, hi_out, L, oy0, i, ring, vs, acc, inv_n);
        rowstep<3>(P, T, gxl, gxh, okl, okh, hi_out, L, oy0, i, ring, vs, acc, inv_n);
        rowstep<4>(P, T, gxl, gxh, okl, okh, hi_out, L, oy0, i, ring, vs, acc, inv_n);
        rowstep<5>(P, T, gxl, gxh, okl, okh, hi_out, L, oy0, i, ring, vs, acc, inv_n);
        rowstep<6>(P, T, gxl, gxh, okl, okh, hi_out, L, oy0, i, ring, vs, acc, inv_n);
    }
    rowstep<0>(P, T, gxl, gxh, okl, okh, hi_out, L, oy0, i, ring, vs, acc, inv_n);
    rowstep<1>(P, T, gxl, gxh, okl, okh, hi_out, L, oy0, i, ring, vs, acc, inv_n);
    rowstep<2>(P, T, gxl, gxh, okl, okh, hi_out, L, oy0, i, ring, vs, acc, inv_n);

    // warp reduce
#pragma unroll
    for (int o = 16; o > 0; o >>= 1)
        acc += __shfl_xor_sync(FULLMASK, acc, o);

    __shared__ float ws[8];
    if (L == 0) ws[w] = acc;
    __syncthreads();
    if (threadIdx.x == 0) {
        float s = 0.f;
#pragma unroll
        for (int k = 0; k < 8; k++) s += ws[k];
        atomicAdd(out, s * (1.0f / (16.0f * 512.0f * 512.0f)));
    }
}

extern "C" void kernel_launch(void* const* d_in, const int* in_sizes, int n_in,
                              void* d_out, int out_size)
{
    const float* pred = (const float*)d_in[0];
    const float* tgt  = (const float*)d_in[1];
    float* out = (float*)d_out;

    cudaMemsetAsync(out, 0, sizeof(float));

    dim3 block(256, 1, 1);
    dim3 grid((W_ + TW - 1) / TW, H_ / 256, 16);   // 9 x 2 x 16 = 288 CTAs
    dist_loss_kernel<<<grid, block>>>(pred, tgt, out);
}

// round 3
// speedup vs baseline: 1.9301x; 1.7766x over previous
#include <cuda_runtime.h>
#include <math.h>

#define W_   512
#define H_   512
#define HW_  (512 * 512)
#define EPS  1e-8f
#define TW   26              // output columns per warp (26 + 6 halo = 32 lanes)
#define FULLMASK 0xffffffffu

__device__ __forceinline__ float sqrt_approx(float x) {
    float r;
    asm("sqrt.approx.f32 %0, %1;" : "=f"(r) : "f"(x));
    return r;
}

// h[L] = sum_{k=0..6} v[L+k] over the warp-distributed 32-vector.
// Lanes >= 26 get garbage (shfl self) — outputs there are predicated off.
__device__ __forceinline__ float hsum7(float v) {
    float d1 = v + __shfl_down_sync(FULLMASK, v, 1);     // 2-sum
    float d2 = d1 + __shfl_down_sync(FULLMASK, d1, 2);   // 4-sum
    float r4 = __shfl_down_sync(FULLMASK, d1, 4);        // v[c+4]+v[c+5]
    float r6 = __shfl_down_sync(FULLMASK, v, 6);         // v[c+6]
    return d2 + (r4 + r6);
}

__device__ __forceinline__ float smooth_l1(float a, float b) {
    float d = a - b;
    float ad = fabsf(d);
    return (ad < 1.0f) ? 0.5f * d * d : ad - 0.5f;
}

// One input row: predicated loads (3 channels x 2 inputs), channel reduce,
// horizontal 7-sum via shuffles, vertical running sum through 7-slot ring
// (compile-time slot S), emit smooth-L1 once warmed up.
template <int S>
__device__ __forceinline__ void rowstep(
    const float* __restrict__ P, const float* __restrict__ T,
    int gx, bool okx, bool out_ok, int oy0,
    int& i, float (&ring)[4][7], float (&vs)[4], float& acc, float inv_n)
{
    const int gy = oy0 - 3 + i;
    const bool ok = okx && (gy >= 0) && (gy < H_);
    const int off = (gy << 9) + gx;

    float h[4];
    {
        float a0 = ok ? P[off]           : 0.f;
        float a1 = ok ? P[off + HW_]     : 0.f;
        float a2 = ok ? P[off + 2 * HW_] : 0.f;
        float v  = a0 + a1 + a2;
        float v2 = fmaf(a0, a0, fmaf(a1, a1, a2 * a2));
        h[0] = hsum7(v);
        h[1] = hsum7(v2);
    }
    {
        float a0 = ok ? T[off]           : 0.f;
        float a1 = ok ? T[off + HW_]     : 0.f;
        float a2 = ok ? T[off + 2 * HW_] : 0.f;
        float v  = a0 + a1 + a2;
        float v2 = fmaf(a0, a0, fmaf(a1, a1, a2 * a2));
        h[2] = hsum7(v);
        h[3] = hsum7(v2);
    }

#pragma unroll
    for (int a = 0; a < 4; a++) {
        vs[a] += h[a] - ring[a][S];
        ring[a][S] = h[a];
    }

    if (i >= 6 && out_ok) {
        float mp = vs[0] * inv_n;
        float sp = sqrt_approx(fmaf(-mp, mp, vs[1] * inv_n) + EPS);
        float mt = vs[2] * inv_n;
        float st = sqrt_approx(fmaf(-mt, mt, vs[3] * inv_n) + EPS);
        acc += smooth_l1(sp, st);
    }
    i++;
}

__global__ __launch_bounds__(128, 6)
void dist_loss_kernel(const float* __restrict__ pred,
                      const float* __restrict__ tgt,
                      float* __restrict__ out)
{
    const int L  = threadIdx.x & 31;
    const int w  = threadIdx.x >> 5;
    const int x0 = blockIdx.x * TW;
    const int oy0 = (blockIdx.y << 7) + (w << 5);     // warp's first output row
    const size_t bofs = (size_t)blockIdx.z * 3 * HW_;
    const float* P = pred + bofs;
    const float* T = tgt + bofs;

    const int gx = x0 - 3 + L;                        // halo-inclusive column
    const bool okx = (gx >= 0) && (gx < W_);
    const bool out_ok = (L < TW) && ((x0 + L) < W_);

    const float inv_n = 1.0f / 147.0f;

    float ring[4][7];
    float vs[4];
#pragma unroll
    for (int a = 0; a < 4; a++) {
        vs[a] = 0.f;
#pragma unroll
        for (int j = 0; j < 7; j++) ring[a][j] = 0.f;
    }

    float acc = 0.f;
    int i = 0;

    // 38 input rows = 5 chunks of 7 ring slots + 3 tail steps
#pragma unroll 1
    for (int c = 0; c < 5; c++) {
        rowstep<0>(P, T, gx, okx, out_ok, oy0, i, ring, vs, acc, inv_n);
        rowstep<1>(P, T, gx, okx, out_ok, oy0, i, ring, vs, acc, inv_n);
        rowstep<2>(P, T, gx, okx, out_ok, oy0, i, ring, vs, acc, inv_n);
        rowstep<3>(P, T, gx, okx, out_ok, oy0, i, ring, vs, acc, inv_n);
        rowstep<4>(P, T, gx, okx, out_ok, oy0, i, ring, vs, acc, inv_n);
        rowstep<5>(P, T, gx, okx, out_ok, oy0, i, ring, vs, acc, inv_n);
        rowstep<6>(P, T, gx, okx, out_ok, oy0, i, ring, vs, acc, inv_n);
    }
    rowstep<0>(P, T, gx, okx, out_ok, oy0, i, ring, vs, acc, inv_n);
    rowstep<1>(P, T, gx, okx, out_ok, oy0, i, ring, vs, acc, inv_n);
    rowstep<2>(P, T, gx, okx, out_ok, oy0, i, ring, vs, acc, inv_n);

    // warp reduce
#pragma unroll
    for (int o = 16; o > 0; o >>= 1)
        acc += __shfl_xor_sync(FULLMASK, acc, o);

    __shared__ float ws[4];
    if (L == 0) ws[w] = acc;
    __syncthreads();
    if (threadIdx.x == 0) {
        float s = ws[0] + ws[1] + ws[2] + ws[3];
        atomicAdd(out, s * (1.0f / (16.0f * 512.0f * 512.0f)));
    }
}

extern "C" void kernel_launch(void* const* d_in, const int* in_sizes, int n_in,
                              void* d_out, int out_size)
{
    const float* pred = (const float*)d_in[0];
    const float* tgt  = (const float*)d_in[1];
    float* out = (float*)d_out;

    cudaMemsetAsync(out, 0, sizeof(float));

    dim3 block(128, 1, 1);
    dim3 grid((W_ + TW - 1) / TW, H_ / 128, 16);   // 20 x 4 x 16 = 1280 CTAs
    dist_loss_kernel<<<grid, block>>>(pred, tgt, out);
}